// round 12
// baseline (speedup 1.0000x reference)
#include <cuda_runtime.h>
#include <math.h>
#include <stdint.h>

#define NN 50000
#define FF 128
#define CC 512
#define EE 800000
#define HH 256

// Output layout: new_x [C,F], new_adj [C,C], new_batch [C], S [N,C]
#define OFF_ADJ   (CC*FF)
#define OFF_BATCH (OFF_ADJ + CC*CC)
#define OFF_S     (OFF_BATCH + CC)

#define EB ((EE + 255) / 256)
#define HSB ((NN * 32 + 255) / 256)
#define INITB 512

// ---------------- scratch ----------------------------------------------------
__device__ __align__(16) float g_h[(size_t)NN * CC];
__device__ __align__(16) float g_z[(size_t)NN * HH];
__device__ float g_inv[NN];
__device__ int   g_deg[NN];
__device__ int   g_off[NN + 1];
__device__ int   g_cur[NN];
__device__ int   g_csr_src[EE];
__device__ float g_csr_cf[EE];
__device__ int   g_cluster[NN];
__device__ float g_hs[NN];
__device__ int   g_sdeg[NN];
__device__ float g_invs[NN];
__device__ float g_sagg[NN];
__device__ float g_score[NN];
__device__ int   g_icnt[CC];
__device__ int   g_segkey[CC];
__device__ int   g_segidx[CC];

__device__ __forceinline__ int fkey(float f) {
    int b = __float_as_int(f);
    return b < 0 ? (b ^ 0x7FFFFFFF) : b;
}
__device__ __forceinline__ float fdec(int k) {
    return __int_as_float(k < 0 ? (k ^ 0x7FFFFFFF) : k);
}

// ---------------- fused init + g_deg zero ------------------------------------
__global__ void k_initdeg(float* out) {
    int bid = blockIdx.x;
    int t = threadIdx.x;
    if (bid < INITB) {
        int i = bid * 256 + t;
        int stride = INITB * 256;
        for (int j = i; j < NN; j += stride) { g_sdeg[j] = 0; g_sagg[j] = 0.f; }
        for (int j = i; j < CC; j += stride) {
            g_icnt[j] = 0; g_segkey[j] = (int)0x80000000; g_segidx[j] = NN;
            out[OFF_BATCH + j] = 0.f;
        }
        for (int j = i; j < CC * CC; j += stride) out[OFF_ADJ + j] = 0.f;
    } else {
        int zi = (bid - INITB) * 256 + t;
        if (zi < NN) g_deg[zi] = 0;
    }
}

// single block: degree histogram + exclusive scan + inv + cur
__global__ void __launch_bounds__(1024) k_scanall(const int* __restrict__ ei) {
    int t = threadIdx.x;
    for (int e = t; e < EE; e += 1024) atomicAdd(&g_deg[ei[EE + e]], 1);
    __syncthreads();

    __shared__ int ssum[1024];
    const int chunk = (NN + 1023) / 1024;
    int b = t * chunk, e = min(b + chunk, NN);
    int s = 0;
    for (int i = b; i < e; i++) s += g_deg[i];
    ssum[t] = s;
    __syncthreads();
    for (int off = 1; off < 1024; off <<= 1) {
        int v = (t >= off) ? ssum[t - off] : 0;
        __syncthreads();
        ssum[t] += v;
        __syncthreads();
    }
    int run = (t > 0) ? ssum[t - 1] : 0;
    for (int i = b; i < e; i++) {
        int d = g_deg[i];
        g_off[i] = run;
        g_cur[i] = run;
        g_inv[i] = rsqrtf((float)d + 1.0f);
        run += d;
    }
    if (t == 1023) g_off[NN] = ssum[1023];
}

__global__ void k_fill(const int* __restrict__ ei) {
    int e = blockIdx.x * blockDim.x + threadIdx.x;
    if (e >= EE) return;
    int s = ei[e], d = ei[EE + e];
    int p = atomicAdd(&g_cur[d], 1);
    g_csr_src[p] = s;
    g_csr_cf[p] = g_inv[s] * g_inv[d];
}

// ---------------- aggregation: 128-wide slice pass, persistent ---------------
// Processes features [foff, foff+128) of rows with stride STRIDE.
// Touched source slice = 50000*512B = 25.6MB -> L2-resident (the measured-fast
// regime: k_agg<128> = 164us).
template <int STRIDE>
__global__ void __launch_bounds__(128) k_aggs(const float* __restrict__ h,
                                              float* __restrict__ z,
                                              int foff) {
    int t = threadIdx.x;
    const float* hf = h + foff + t;
    for (int i = blockIdx.x; i < NN; i += gridDim.x) {
        int beg = g_off[i], end = g_off[i + 1];
        float inv = g_inv[i];
        float acc0 = inv * inv * __ldg(hf + (size_t)i * STRIDE);
        float acc1 = 0.f;

        int j = beg;
        for (; j + 8 <= end; j += 8) {
            int s0 = __ldg(g_csr_src + j + 0);
            int s1 = __ldg(g_csr_src + j + 1);
            int s2 = __ldg(g_csr_src + j + 2);
            int s3 = __ldg(g_csr_src + j + 3);
            int s4 = __ldg(g_csr_src + j + 4);
            int s5 = __ldg(g_csr_src + j + 5);
            int s6 = __ldg(g_csr_src + j + 6);
            int s7 = __ldg(g_csr_src + j + 7);
            float c0 = __ldg(g_csr_cf + j + 0);
            float c1 = __ldg(g_csr_cf + j + 1);
            float c2 = __ldg(g_csr_cf + j + 2);
            float c3 = __ldg(g_csr_cf + j + 3);
            float c4 = __ldg(g_csr_cf + j + 4);
            float c5 = __ldg(g_csr_cf + j + 5);
            float c6 = __ldg(g_csr_cf + j + 6);
            float c7 = __ldg(g_csr_cf + j + 7);
            float v0 = __ldg(hf + (size_t)s0 * STRIDE);
            float v1 = __ldg(hf + (size_t)s1 * STRIDE);
            float v2 = __ldg(hf + (size_t)s2 * STRIDE);
            float v3 = __ldg(hf + (size_t)s3 * STRIDE);
            float v4 = __ldg(hf + (size_t)s4 * STRIDE);
            float v5 = __ldg(hf + (size_t)s5 * STRIDE);
            float v6 = __ldg(hf + (size_t)s6 * STRIDE);
            float v7 = __ldg(hf + (size_t)s7 * STRIDE);
            acc0 = fmaf(c0, v0, acc0); acc1 = fmaf(c1, v1, acc1);
            acc0 = fmaf(c2, v2, acc0); acc1 = fmaf(c3, v3, acc1);
            acc0 = fmaf(c4, v4, acc0); acc1 = fmaf(c5, v5, acc1);
            acc0 = fmaf(c6, v6, acc0); acc1 = fmaf(c7, v7, acc1);
        }
        for (; j < end; j++) {
            int s0 = __ldg(g_csr_src + j);
            float c0 = __ldg(g_csr_cf + j);
            acc0 = fmaf(c0, __ldg(hf + (size_t)s0 * STRIDE), acc0);
        }
        z[(size_t)i * STRIDE + foff + t] = acc0 + acc1;
    }
}

// ---------------- split-tf32 TC GEMM, software-pipelined ---------------------
__device__ __forceinline__ uint32_t f2tf(float f) {
    uint32_t r;
    asm("cvt.rna.tf32.f32 %0, %1;" : "=r"(r) : "f"(f));
    return r;
}
__device__ __forceinline__ void mma_tf32(float4& d,
                                         uint32_t a0, uint32_t a1, uint32_t a2, uint32_t a3,
                                         uint32_t b0, uint32_t b1) {
    asm volatile("mma.sync.aligned.m16n8k8.row.col.f32.tf32.tf32.f32 "
                 "{%0,%1,%2,%3}, {%4,%5,%6,%7}, {%8,%9}, {%0,%1,%2,%3};"
                 : "+f"(d.x), "+f"(d.y), "+f"(d.z), "+f"(d.w)
                 : "r"(a0), "r"(a1), "r"(a2), "r"(a3), "r"(b0), "r"(b1));
}

#define TCSTRIDE 136

__global__ void __launch_bounds__(256) k_tcgemm(const float* __restrict__ A,
                                                const float* __restrict__ B,
                                                const float* __restrict__ bias,
                                                float* __restrict__ Cm,
                                                int M, int K, int Nc) {
    __shared__ uint32_t Ah[2][8][TCSTRIDE];
    __shared__ uint32_t Al[2][8][TCSTRIDE];
    __shared__ uint32_t Bh[2][8][TCSTRIDE];
    __shared__ uint32_t Bl[2][8][TCSTRIDE];

    const int tid = threadIdx.x;
    const int wid = tid >> 5;
    const int lane = tid & 31;
    const int q = lane >> 2;
    const int t4 = lane & 3;
    const int m0 = (wid & 3) * 32;
    const int n0 = (wid >> 2) * 64;

    const int rowBase = blockIdx.y * 128;
    const int colBase = blockIdx.x * 128;

    const int ar = tid >> 1;
    const int ac4 = (tid & 1) * 4;
    const int br = tid >> 5;
    const int bc4 = (tid & 31) * 4;
    const bool aok = (rowBase + ar) < M;
    const float* Aptr = A + (size_t)(rowBase + ar) * K + ac4;
    const float* Bptr = B + (size_t)br * Nc + colBase + bc4;

    float4 acc[2][8];
#pragma unroll
    for (int mi = 0; mi < 2; mi++)
#pragma unroll
        for (int ni = 0; ni < 8; ni++) acc[mi][ni] = make_float4(0.f, 0.f, 0.f, 0.f);

#define SPLIT_STORE(arrH, arrL, BUF, D0, D1, V)                      \
    {                                                                \
        uint32_t h_ = f2tf(V);                                       \
        float lo_ = (V) - __uint_as_float(h_);                       \
        arrH[BUF][D0][D1] = h_;                                      \
        arrL[BUF][D0][D1] = f2tf(lo_);                               \
    }
#define STORE_TILE(BUF, VA, VB)                                                   \
    {                                                                             \
        SPLIT_STORE(Ah, Al, BUF, ac4 + 0, ar, (VA).x)                             \
        SPLIT_STORE(Ah, Al, BUF, ac4 + 1, ar, (VA).y)                             \
        SPLIT_STORE(Ah, Al, BUF, ac4 + 2, ar, (VA).z)                             \
        SPLIT_STORE(Ah, Al, BUF, ac4 + 3, ar, (VA).w)                             \
        SPLIT_STORE(Bh, Bl, BUF, br, bc4 + 0, (VB).x)                             \
        SPLIT_STORE(Bh, Bl, BUF, br, bc4 + 1, (VB).y)                             \
        SPLIT_STORE(Bh, Bl, BUF, br, bc4 + 2, (VB).z)                             \
        SPLIT_STORE(Bh, Bl, BUF, br, bc4 + 3, (VB).w)                             \
    }

#define COMPUTE_TILE(BUF)                                                          \
    {                                                                              \
        uint32_t ah[2][4], al[2][4];                                               \
        _Pragma("unroll")                                                          \
        for (int mi = 0; mi < 2; mi++) {                                           \
            int mrow = m0 + mi * 16;                                               \
            ah[mi][0] = Ah[BUF][t4][mrow + q];                                     \
            ah[mi][1] = Ah[BUF][t4][mrow + q + 8];                                 \
            ah[mi][2] = Ah[BUF][t4 + 4][mrow + q];                                 \
            ah[mi][3] = Ah[BUF][t4 + 4][mrow + q + 8];                             \
            al[mi][0] = Al[BUF][t4][mrow + q];                                     \
            al[mi][1] = Al[BUF][t4][mrow + q + 8];                                 \
            al[mi][2] = Al[BUF][t4 + 4][mrow + q];                                 \
            al[mi][3] = Al[BUF][t4 + 4][mrow + q + 8];                             \
        }                                                                          \
        _Pragma("unroll")                                                          \
        for (int ni = 0; ni < 8; ni++) {                                           \
            int ncol = n0 + ni * 8 + q;                                            \
            uint32_t bh0 = Bh[BUF][t4][ncol];                                      \
            uint32_t bh1 = Bh[BUF][t4 + 4][ncol];                                  \
            uint32_t bl0 = Bl[BUF][t4][ncol];                                      \
            uint32_t bl1 = Bl[BUF][t4 + 4][ncol];                                  \
            _Pragma("unroll")                                                      \
            for (int mi = 0; mi < 2; mi++) {                                       \
                mma_tf32(acc[mi][ni], ah[mi][0], ah[mi][1], ah[mi][2], ah[mi][3],  \
                         bh0, bh1);                                                \
                mma_tf32(acc[mi][ni], ah[mi][0], ah[mi][1], ah[mi][2], ah[mi][3],  \
                         bl0, bl1);                                                \
                mma_tf32(acc[mi][ni], al[mi][0], al[mi][1], al[mi][2], al[mi][3],  \
                         bh0, bh1);                                                \
            }                                                                      \
        }                                                                          \
    }

    {
        float4 va = aok ? *(const float4*)Aptr : make_float4(0.f, 0.f, 0.f, 0.f);
        float4 vb = *(const float4*)Bptr;
        STORE_TILE(0, va, vb)
    }
    __syncthreads();

    int buf = 0;
    for (int k0 = 8; k0 < K; k0 += 8) {
        float4 va = aok ? *(const float4*)(Aptr + k0) : make_float4(0.f, 0.f, 0.f, 0.f);
        float4 vb = *(const float4*)(Bptr + (size_t)k0 * Nc);
        COMPUTE_TILE(buf)
        STORE_TILE(buf ^ 1, va, vb)
        __syncthreads();
        buf ^= 1;
    }
    COMPUTE_TILE(buf)

#pragma unroll
    for (int mi = 0; mi < 2; mi++) {
#pragma unroll
        for (int ni = 0; ni < 8; ni++) {
            int col = colBase + n0 + ni * 8 + 2 * t4;
            float bb0 = bias[col], bb1 = bias[col + 1];
            int r0 = rowBase + m0 + mi * 16 + q;
            int r1 = r0 + 8;
            float4 v = acc[mi][ni];
            float o0 = fmaxf(v.x + bb0, 0.f);
            float o1 = fmaxf(v.y + bb1, 0.f);
            float o2 = fmaxf(v.z + bb0, 0.f);
            float o3 = fmaxf(v.w + bb1, 0.f);
            if (r0 < M) *(float2*)(Cm + (size_t)r0 * Nc + col) = make_float2(o0, o1);
            if (r1 < M) *(float2*)(Cm + (size_t)r1 * Nc + col) = make_float2(o2, o3);
        }
    }
}

// ---------------- softmax + argmax: persistent grid-stride -------------------
__global__ void __launch_bounds__(256) k_softmax(const float* __restrict__ logits,
                                                 float* __restrict__ S) {
    int t = threadIdx.x;
    __shared__ float sv[256];
    __shared__ int   si[256];
    for (int i = blockIdx.x; i < NN; i += gridDim.x) {
        const float* row = logits + (size_t)i * CC;
        float v0 = row[t], v1 = row[t + 256];
        float bv = v0; int bi = t;
        if (v1 > bv) { bv = v1; bi = t + 256; }

        sv[t] = bv; si[t] = bi;
        __syncthreads();
        for (int s = 128; s > 0; s >>= 1) {
            if (t < s) {
                float ov = sv[t + s]; int oi = si[t + s];
                if (ov > sv[t] || (ov == sv[t] && oi < si[t])) { sv[t] = ov; si[t] = oi; }
            }
            __syncthreads();
        }
        float m = sv[0];
        if (t == 0) g_cluster[i] = si[0];
        __syncthreads();

        float e0 = expf(v0 - m), e1 = expf(v1 - m);
        sv[t] = e0 + e1;
        __syncthreads();
        for (int s = 128; s > 0; s >>= 1) {
            if (t < s) sv[t] += sv[t + s];
            __syncthreads();
        }
        float invsum = 1.0f / sv[0];
        S[(size_t)i * CC + t]       = e0 * invsum;
        S[(size_t)i * CC + t + 256] = e1 * invsum;
        __syncthreads();
    }
}

// ---------------- fused: hs (x@Ws) + intradeg --------------------------------
__global__ void k_hsintra(const float* __restrict__ x,
                          const float* __restrict__ Ws,
                          const int* __restrict__ ei) {
    int bid = blockIdx.x;
    int t = threadIdx.x;
    if (bid < HSB) {
        int g = bid * 256 + t;
        int w = g >> 5, lane = g & 31;
        if (w >= NN) return;
        float s = 0.f;
        for (int f = lane; f < FF; f += 32) s = fmaf(x[(size_t)w * FF + f], Ws[f], s);
#pragma unroll
        for (int off = 16; off > 0; off >>= 1) s += __shfl_down_sync(0xFFFFFFFF, s, off);
        if (lane == 0) g_hs[w] = s;
    } else {
        int e = (bid - HSB) * 256 + t;
        if (e >= EE) return;
        int s = ei[e], d = ei[EE + e];
        int cs = g_cluster[s], cd = g_cluster[d];
        if (cs == cd) {
            atomicAdd(&g_sdeg[d], 1);
            atomicAdd(&g_icnt[cs], 1);
        }
    }
}

__global__ void k_invs() {
    int i = blockIdx.x * blockDim.x + threadIdx.x;
    if (i < NN) g_invs[i] = rsqrtf((float)g_sdeg[i] + 1.0f);
}

__global__ void k_sagg(const int* __restrict__ ei) {
    int e = blockIdx.x * blockDim.x + threadIdx.x;
    if (e >= EE) return;
    int s = ei[e], d = ei[EE + e];
    if (g_cluster[s] == g_cluster[d])
        atomicAdd(&g_sagg[d], g_invs[s] * g_invs[d] * g_hs[s]);
}

__global__ void k_score(const float* __restrict__ bs) {
    int i = blockIdx.x * blockDim.x + threadIdx.x;
    if (i >= NN) return;
    float inv = g_invs[i];
    float v = g_sagg[i] + inv * inv * g_hs[i] + bs[0];
    float sc = tanhf(v);
    g_score[i] = sc;
    atomicMax(&g_segkey[g_cluster[i]], fkey(sc));
}

__global__ void k_segidx() {
    int i = blockIdx.x * blockDim.x + threadIdx.x;
    if (i >= NN) return;
    int c = g_cluster[i];
    float mx = fdec(g_segkey[c]);
    if (g_score[i] >= mx) atomicMin(&g_segidx[c], i);
}

// ---------------- fused: pool + adjacency ------------------------------------
__global__ void k_pooladj(const float* __restrict__ x,
                          const int* __restrict__ ei,
                          float* __restrict__ out) {
    int bid = blockIdx.x;
    int t = threadIdx.x;
    if (bid < CC) {
        if (t < 128) {
            int c = bid;
            bool ne = g_icnt[c] > 0;
            float alpha = ne ? fdec(g_segkey[c]) : 0.f;
            int idx = min(g_segidx[c], NN - 1);
            out[(size_t)c * FF + t] = x[(size_t)idx * FF + t] * alpha;
        }
    } else {
        int e = (bid - CC) * 256 + t;
        if (e >= EE) return;
        int cs = g_cluster[ei[e]], cd = g_cluster[ei[EE + e]];
        if (cs != cd && g_icnt[cs] > 0 && g_icnt[cd] > 0)
            out[OFF_ADJ + (size_t)cs * CC + cd] = 1.0f;
    }
}

// ---------------- launch ------------------------------------------------------
extern "C" void kernel_launch(void* const* d_in, const int* in_sizes, int n_in,
                              void* d_out, int out_size) {
    const float* x   = (const float*)d_in[0];
    const int*   ei  = (const int*)d_in[1];
    const float* W1  = (const float*)d_in[3];
    const float* b1  = (const float*)d_in[4];
    const float* W2  = (const float*)d_in[5];
    const float* b2  = (const float*)d_in[6];
    const float* W3  = (const float*)d_in[7];
    const float* b3  = (const float*)d_in[8];
    const float* Ws  = (const float*)d_in[9];
    const float* bs  = (const float*)d_in[10];
    float* out = (float*)d_out;

    const int NB = (NN + 255) / 256;
    const int PG128 = 148 * 16;
    const int PG256 = 148 * 8;

    k_initdeg<<<INITB + NB, 256>>>(out);       // 0
    k_scanall<<<1, 1024>>>(ei);                // 1
    k_fill<<<EB, 256>>>(ei);                   // 2
    k_aggs<128><<<PG128, 128>>>(x, g_z, 0);    // 3  [PROFILED sentinel]
    {
        dim3 g(HH / 128, (NN + 127) / 128);
        k_tcgemm<<<g, 256>>>(g_z, W1, b1, g_h, NN, FF, HH);
    }
    // layer 2 agg: two L2-resident half passes over g_h (stride 256)
    k_aggs<256><<<PG128, 128>>>(g_h, g_z, 0);
    k_aggs<256><<<PG128, 128>>>(g_h, g_z, 128);
    {
        dim3 g(HH / 128, (NN + 127) / 128);
        k_tcgemm<<<g, 256>>>(g_z, W2, b2, g_h, NN, HH, HH);
    }
    // layer 3 agg: same
    k_aggs<256><<<PG128, 128>>>(g_h, g_z, 0);
    k_aggs<256><<<PG128, 128>>>(g_h, g_z, 128);
    {
        dim3 g(CC / 128, (NN + 127) / 128);
        k_tcgemm<<<g, 256>>>(g_z, W3, b3, g_h, NN, HH, CC);
    }

    k_softmax<<<PG256, 256>>>(g_h, out + OFF_S);

    k_hsintra<<<HSB + EB, 256>>>(x, Ws, ei);
    k_invs<<<NB, 256>>>();
    k_sagg<<<EB, 256>>>(ei);
    k_score<<<NB, 256>>>(bs);
    k_segidx<<<NB, 256>>>();
    k_pooladj<<<CC + EB, 256>>>(x, ei, out);

    (void)in_sizes; (void)n_in; (void)out_size;
}

// round 14
// speedup vs baseline: 6.9019x; 6.9019x over previous
#include <cuda_runtime.h>
#include <math.h>
#include <stdint.h>

#define NN 50000
#define FF 128
#define CC 512
#define EE 800000
#define HH 256

// Output layout: new_x [C,F], new_adj [C,C], new_batch [C], S [N,C]
#define OFF_ADJ   (CC*FF)
#define OFF_BATCH (OFF_ADJ + CC*CC)
#define OFF_S     (OFF_BATCH + CC)

#define EB ((EE + 255) / 256)
#define HSB ((NN * 32 + 255) / 256)
#define INITB 512

// ---------------- scratch ----------------------------------------------------
__device__ __align__(16) float g_h[(size_t)NN * CC];
__device__ __align__(16) float g_z[(size_t)NN * HH];
__device__ float g_inv[NN];
__device__ int   g_deg[NN];
__device__ int   g_off[NN + 1];
__device__ int   g_cur[NN];
__device__ int   g_csr_src[EE];
__device__ float g_csr_cf[EE];
__device__ int   g_cluster[NN];
__device__ float g_hs[NN];
__device__ int   g_sdeg[NN];
__device__ float g_invs[NN];
__device__ float g_sagg[NN];
__device__ float g_score[NN];
__device__ int   g_icnt[CC];
__device__ int   g_segkey[CC];
__device__ int   g_segidx[CC];

__device__ __forceinline__ int fkey(float f) {
    int b = __float_as_int(f);
    return b < 0 ? (b ^ 0x7FFFFFFF) : b;
}
__device__ __forceinline__ float fdec(int k) {
    return __int_as_float(k < 0 ? (k ^ 0x7FFFFFFF) : k);
}

// ---------------- fused init + g_deg zero ------------------------------------
__global__ void k_initdeg(float* out) {
    int bid = blockIdx.x;
    int t = threadIdx.x;
    if (bid < INITB) {
        int i = bid * 256 + t;
        int stride = INITB * 256;
        for (int j = i; j < NN; j += stride) { g_sdeg[j] = 0; g_sagg[j] = 0.f; }
        for (int j = i; j < CC; j += stride) {
            g_icnt[j] = 0; g_segkey[j] = (int)0x80000000; g_segidx[j] = NN;
            out[OFF_BATCH + j] = 0.f;
        }
        for (int j = i; j < CC * CC; j += stride) out[OFF_ADJ + j] = 0.f;
    } else {
        int zi = (bid - INITB) * 256 + t;
        if (zi < NN) g_deg[zi] = 0;
    }
}

// single block: degree histogram + exclusive scan + inv + cur
__global__ void __launch_bounds__(1024) k_scanall(const int* __restrict__ ei) {
    int t = threadIdx.x;
    for (int e = t; e < EE; e += 1024) atomicAdd(&g_deg[ei[EE + e]], 1);
    __syncthreads();

    __shared__ int ssum[1024];
    const int chunk = (NN + 1023) / 1024;
    int b = t * chunk, e = min(b + chunk, NN);
    int s = 0;
    for (int i = b; i < e; i++) s += g_deg[i];
    ssum[t] = s;
    __syncthreads();
    for (int off = 1; off < 1024; off <<= 1) {
        int v = (t >= off) ? ssum[t - off] : 0;
        __syncthreads();
        ssum[t] += v;
        __syncthreads();
    }
    int run = (t > 0) ? ssum[t - 1] : 0;
    for (int i = b; i < e; i++) {
        int d = g_deg[i];
        g_off[i] = run;
        g_cur[i] = run;
        g_inv[i] = rsqrtf((float)d + 1.0f);
        run += d;
    }
    if (t == 1023) g_off[NN] = ssum[1023];
}

__global__ void k_fill(const int* __restrict__ ei) {
    int e = blockIdx.x * blockDim.x + threadIdx.x;
    if (e >= EE) return;
    int s = ei[e], d = ei[EE + e];
    int p = atomicAdd(&g_cur[d], 1);
    g_csr_src[p] = s;
    g_csr_cf[p] = g_inv[s] * g_inv[d];
}

// ---------------- aggregation: 128-wide slice pass, persistent ---------------
template <int STRIDE>
__global__ void __launch_bounds__(128) k_aggs(const float* __restrict__ h,
                                              float* __restrict__ z,
                                              int foff) {
    int t = threadIdx.x;
    const float* hf = h + foff + t;
    for (int i = blockIdx.x; i < NN; i += gridDim.x) {
        int beg = g_off[i], end = g_off[i + 1];
        float inv = g_inv[i];
        float acc0 = inv * inv * __ldg(hf + (size_t)i * STRIDE);
        float acc1 = 0.f;

        int j = beg;
        for (; j + 8 <= end; j += 8) {
            int s0 = __ldg(g_csr_src + j + 0);
            int s1 = __ldg(g_csr_src + j + 1);
            int s2 = __ldg(g_csr_src + j + 2);
            int s3 = __ldg(g_csr_src + j + 3);
            int s4 = __ldg(g_csr_src + j + 4);
            int s5 = __ldg(g_csr_src + j + 5);
            int s6 = __ldg(g_csr_src + j + 6);
            int s7 = __ldg(g_csr_src + j + 7);
            float c0 = __ldg(g_csr_cf + j + 0);
            float c1 = __ldg(g_csr_cf + j + 1);
            float c2 = __ldg(g_csr_cf + j + 2);
            float c3 = __ldg(g_csr_cf + j + 3);
            float c4 = __ldg(g_csr_cf + j + 4);
            float c5 = __ldg(g_csr_cf + j + 5);
            float c6 = __ldg(g_csr_cf + j + 6);
            float c7 = __ldg(g_csr_cf + j + 7);
            float v0 = __ldg(hf + (size_t)s0 * STRIDE);
            float v1 = __ldg(hf + (size_t)s1 * STRIDE);
            float v2 = __ldg(hf + (size_t)s2 * STRIDE);
            float v3 = __ldg(hf + (size_t)s3 * STRIDE);
            float v4 = __ldg(hf + (size_t)s4 * STRIDE);
            float v5 = __ldg(hf + (size_t)s5 * STRIDE);
            float v6 = __ldg(hf + (size_t)s6 * STRIDE);
            float v7 = __ldg(hf + (size_t)s7 * STRIDE);
            acc0 = fmaf(c0, v0, acc0); acc1 = fmaf(c1, v1, acc1);
            acc0 = fmaf(c2, v2, acc0); acc1 = fmaf(c3, v3, acc1);
            acc0 = fmaf(c4, v4, acc0); acc1 = fmaf(c5, v5, acc1);
            acc0 = fmaf(c6, v6, acc0); acc1 = fmaf(c7, v7, acc1);
        }
        for (; j < end; j++) {
            int s0 = __ldg(g_csr_src + j);
            float c0 = __ldg(g_csr_cf + j);
            acc0 = fmaf(c0, __ldg(hf + (size_t)s0 * STRIDE), acc0);
        }
        z[(size_t)i * STRIDE + foff + t] = acc0 + acc1;
    }
}

// ---------------- split-tf32 TC GEMM, software-pipelined ---------------------
__device__ __forceinline__ uint32_t f2tf(float f) {
    uint32_t r;
    asm("cvt.rna.tf32.f32 %0, %1;" : "=r"(r) : "f"(f));
    return r;
}
__device__ __forceinline__ void mma_tf32(float4& d,
                                         uint32_t a0, uint32_t a1, uint32_t a2, uint32_t a3,
                                         uint32_t b0, uint32_t b1) {
    asm volatile("mma.sync.aligned.m16n8k8.row.col.f32.tf32.tf32.f32 "
                 "{%0,%1,%2,%3}, {%4,%5,%6,%7}, {%8,%9}, {%0,%1,%2,%3};"
                 : "+f"(d.x), "+f"(d.y), "+f"(d.z), "+f"(d.w)
                 : "r"(a0), "r"(a1), "r"(a2), "r"(a3), "r"(b0), "r"(b1));
}

#define TCSTRIDE 136

__global__ void __launch_bounds__(256) k_tcgemm(const float* __restrict__ A,
                                                const float* __restrict__ B,
                                                const float* __restrict__ bias,
                                                float* __restrict__ Cm,
                                                int M, int K, int Nc) {
    __shared__ uint32_t Ah[2][8][TCSTRIDE];
    __shared__ uint32_t Al[2][8][TCSTRIDE];
    __shared__ uint32_t Bh[2][8][TCSTRIDE];
    __shared__ uint32_t Bl[2][8][TCSTRIDE];

    const int tid = threadIdx.x;
    const int wid = tid >> 5;
    const int lane = tid & 31;
    const int q = lane >> 2;
    const int t4 = lane & 3;
    const int m0 = (wid & 3) * 32;
    const int n0 = (wid >> 2) * 64;

    const int rowBase = blockIdx.y * 128;
    const int colBase = blockIdx.x * 128;

    const int ar = tid >> 1;
    const int ac4 = (tid & 1) * 4;
    const int br = tid >> 5;
    const int bc4 = (tid & 31) * 4;
    const bool aok = (rowBase + ar) < M;
    const float* Aptr = A + (size_t)(rowBase + ar) * K + ac4;
    const float* Bptr = B + (size_t)br * Nc + colBase + bc4;

    float4 acc[2][8];
#pragma unroll
    for (int mi = 0; mi < 2; mi++)
#pragma unroll
        for (int ni = 0; ni < 8; ni++) acc[mi][ni] = make_float4(0.f, 0.f, 0.f, 0.f);

#define SPLIT_STORE(arrH, arrL, BUF, D0, D1, V)                      \
    {                                                                \
        uint32_t h_ = f2tf(V);                                       \
        float lo_ = (V) - __uint_as_float(h_);                       \
        arrH[BUF][D0][D1] = h_;                                      \
        arrL[BUF][D0][D1] = f2tf(lo_);                               \
    }
#define STORE_TILE(BUF, VA, VB)                                                   \
    {                                                                             \
        SPLIT_STORE(Ah, Al, BUF, ac4 + 0, ar, (VA).x)                             \
        SPLIT_STORE(Ah, Al, BUF, ac4 + 1, ar, (VA).y)                             \
        SPLIT_STORE(Ah, Al, BUF, ac4 + 2, ar, (VA).z)                             \
        SPLIT_STORE(Ah, Al, BUF, ac4 + 3, ar, (VA).w)                             \
        SPLIT_STORE(Bh, Bl, BUF, br, bc4 + 0, (VB).x)                             \
        SPLIT_STORE(Bh, Bl, BUF, br, bc4 + 1, (VB).y)                             \
        SPLIT_STORE(Bh, Bl, BUF, br, bc4 + 2, (VB).z)                             \
        SPLIT_STORE(Bh, Bl, BUF, br, bc4 + 3, (VB).w)                             \
    }

#define COMPUTE_TILE(BUF)                                                          \
    {                                                                              \
        uint32_t ah[2][4], al[2][4];                                               \
        _Pragma("unroll")                                                          \
        for (int mi = 0; mi < 2; mi++) {                                           \
            int mrow = m0 + mi * 16;                                               \
            ah[mi][0] = Ah[BUF][t4][mrow + q];                                     \
            ah[mi][1] = Ah[BUF][t4][mrow + q + 8];                                 \
            ah[mi][2] = Ah[BUF][t4 + 4][mrow + q];                                 \
            ah[mi][3] = Ah[BUF][t4 + 4][mrow + q + 8];                             \
            al[mi][0] = Al[BUF][t4][mrow + q];                                     \
            al[mi][1] = Al[BUF][t4][mrow + q + 8];                                 \
            al[mi][2] = Al[BUF][t4 + 4][mrow + q];                                 \
            al[mi][3] = Al[BUF][t4 + 4][mrow + q + 8];                             \
        }                                                                          \
        _Pragma("unroll")                                                          \
        for (int ni = 0; ni < 8; ni++) {                                           \
            int ncol = n0 + ni * 8 + q;                                            \
            uint32_t bh0 = Bh[BUF][t4][ncol];                                      \
            uint32_t bh1 = Bh[BUF][t4 + 4][ncol];                                  \
            uint32_t bl0 = Bl[BUF][t4][ncol];                                      \
            uint32_t bl1 = Bl[BUF][t4 + 4][ncol];                                  \
            _Pragma("unroll")                                                      \
            for (int mi = 0; mi < 2; mi++) {                                       \
                mma_tf32(acc[mi][ni], ah[mi][0], ah[mi][1], ah[mi][2], ah[mi][3],  \
                         bh0, bh1);                                                \
                mma_tf32(acc[mi][ni], ah[mi][0], ah[mi][1], ah[mi][2], ah[mi][3],  \
                         bl0, bl1);                                                \
                mma_tf32(acc[mi][ni], al[mi][0], al[mi][1], al[mi][2], al[mi][3],  \
                         bh0, bh1);                                                \
            }                                                                      \
        }                                                                          \
    }

    {
        float4 va = aok ? *(const float4*)Aptr : make_float4(0.f, 0.f, 0.f, 0.f);
        float4 vb = *(const float4*)Bptr;
        STORE_TILE(0, va, vb)
    }
    __syncthreads();

    int buf = 0;
    for (int k0 = 8; k0 < K; k0 += 8) {
        float4 va = aok ? *(const float4*)(Aptr + k0) : make_float4(0.f, 0.f, 0.f, 0.f);
        float4 vb = *(const float4*)(Bptr + (size_t)k0 * Nc);
        COMPUTE_TILE(buf)
        STORE_TILE(buf ^ 1, va, vb)
        __syncthreads();
        buf ^= 1;
    }
    COMPUTE_TILE(buf)

#pragma unroll
    for (int mi = 0; mi < 2; mi++) {
#pragma unroll
        for (int ni = 0; ni < 8; ni++) {
            int col = colBase + n0 + ni * 8 + 2 * t4;
            float bb0 = bias[col], bb1 = bias[col + 1];
            int r0 = rowBase + m0 + mi * 16 + q;
            int r1 = r0 + 8;
            float4 v = acc[mi][ni];
            float o0 = fmaxf(v.x + bb0, 0.f);
            float o1 = fmaxf(v.y + bb1, 0.f);
            float o2 = fmaxf(v.z + bb0, 0.f);
            float o3 = fmaxf(v.w + bb1, 0.f);
            if (r0 < M) *(float2*)(Cm + (size_t)r0 * Nc + col) = make_float2(o0, o1);
            if (r1 < M) *(float2*)(Cm + (size_t)r1 * Nc + col) = make_float2(o2, o3);
        }
    }
}

// ---------------- softmax + argmax: persistent grid-stride -------------------
__global__ void __launch_bounds__(256) k_softmax(const float* __restrict__ logits,
                                                 float* __restrict__ S) {
    int t = threadIdx.x;
    __shared__ float sv[256];
    __shared__ int   si[256];
    for (int i = blockIdx.x; i < NN; i += gridDim.x) {
        const float* row = logits + (size_t)i * CC;
        float v0 = row[t], v1 = row[t + 256];
        float bv = v0; int bi = t;
        if (v1 > bv) { bv = v1; bi = t + 256; }

        sv[t] = bv; si[t] = bi;
        __syncthreads();
        for (int s = 128; s > 0; s >>= 1) {
            if (t < s) {
                float ov = sv[t + s]; int oi = si[t + s];
                if (ov > sv[t] || (ov == sv[t] && oi < si[t])) { sv[t] = ov; si[t] = oi; }
            }
            __syncthreads();
        }
        float m = sv[0];
        if (t == 0) g_cluster[i] = si[0];
        __syncthreads();

        float e0 = expf(v0 - m), e1 = expf(v1 - m);
        sv[t] = e0 + e1;
        __syncthreads();
        for (int s = 128; s > 0; s >>= 1) {
            if (t < s) sv[t] += sv[t + s];
            __syncthreads();
        }
        float invsum = 1.0f / sv[0];
        S[(size_t)i * CC + t]       = e0 * invsum;
        S[(size_t)i * CC + t + 256] = e1 * invsum;
        __syncthreads();
    }
}

// ---------------- fused: hs (x@Ws) + intradeg --------------------------------
__global__ void k_hsintra(const float* __restrict__ x,
                          const float* __restrict__ Ws,
                          const int* __restrict__ ei) {
    int bid = blockIdx.x;
    int t = threadIdx.x;
    if (bid < HSB) {
        int g = bid * 256 + t;
        int w = g >> 5, lane = g & 31;
        if (w >= NN) return;
        float s = 0.f;
        for (int f = lane; f < FF; f += 32) s = fmaf(x[(size_t)w * FF + f], Ws[f], s);
#pragma unroll
        for (int off = 16; off > 0; off >>= 1) s += __shfl_down_sync(0xFFFFFFFF, s, off);
        if (lane == 0) g_hs[w] = s;
    } else {
        int e = (bid - HSB) * 256 + t;
        if (e >= EE) return;
        int s = ei[e], d = ei[EE + e];
        int cs = g_cluster[s], cd = g_cluster[d];
        if (cs == cd) {
            atomicAdd(&g_sdeg[d], 1);
            atomicAdd(&g_icnt[cs], 1);
        }
    }
}

__global__ void k_invs() {
    int i = blockIdx.x * blockDim.x + threadIdx.x;
    if (i < NN) g_invs[i] = rsqrtf((float)g_sdeg[i] + 1.0f);
}

__global__ void k_sagg(const int* __restrict__ ei) {
    int e = blockIdx.x * blockDim.x + threadIdx.x;
    if (e >= EE) return;
    int s = ei[e], d = ei[EE + e];
    if (g_cluster[s] == g_cluster[d])
        atomicAdd(&g_sagg[d], g_invs[s] * g_invs[d] * g_hs[s]);
}

__global__ void k_score(const float* __restrict__ bs) {
    int i = blockIdx.x * blockDim.x + threadIdx.x;
    if (i >= NN) return;
    float inv = g_invs[i];
    float v = g_sagg[i] + inv * inv * g_hs[i] + bs[0];
    float sc = tanhf(v);
    g_score[i] = sc;
    atomicMax(&g_segkey[g_cluster[i]], fkey(sc));
}

__global__ void k_segidx() {
    int i = blockIdx.x * blockDim.x + threadIdx.x;
    if (i >= NN) return;
    int c = g_cluster[i];
    float mx = fdec(g_segkey[c]);
    if (g_score[i] >= mx) atomicMin(&g_segidx[c], i);
}

// ---------------- fused: pool + adjacency ------------------------------------
__global__ void k_pooladj(const float* __restrict__ x,
                          const int* __restrict__ ei,
                          float* __restrict__ out) {
    int bid = blockIdx.x;
    int t = threadIdx.x;
    if (bid < CC) {
        if (t < 128) {
            int c = bid;
            bool ne = g_icnt[c] > 0;
            float alpha = ne ? fdec(g_segkey[c]) : 0.f;
            int idx = min(g_segidx[c], NN - 1);
            out[(size_t)c * FF + t] = x[(size_t)idx * FF + t] * alpha;
        }
    } else {
        int e = (bid - CC) * 256 + t;
        if (e >= EE) return;
        int cs = g_cluster[ei[e]], cd = g_cluster[ei[EE + e]];
        if (cs != cd && g_icnt[cs] > 0 && g_icnt[cd] > 0)
            out[OFF_ADJ + (size_t)cs * CC + cd] = 1.0f;
    }
}

// ---------------- launch ------------------------------------------------------
extern "C" void kernel_launch(void* const* d_in, const int* in_sizes, int n_in,
                              void* d_out, int out_size) {
    const float* x   = (const float*)d_in[0];
    const int*   ei  = (const int*)d_in[1];
    const float* W1  = (const float*)d_in[3];
    const float* b1  = (const float*)d_in[4];
    const float* W2  = (const float*)d_in[5];
    const float* b2  = (const float*)d_in[6];
    const float* W3  = (const float*)d_in[7];
    const float* b3  = (const float*)d_in[8];
    const float* Ws  = (const float*)d_in[9];
    const float* bs  = (const float*)d_in[10];
    float* out = (float*)d_out;

    // CRITICAL: get TRUE device addresses of the scratch symbols.  Passing the
    // array names directly from host code hands kernels the host shadow's
    // address, which GB300's ATS happily services from HOST memory over
    // NVLink-C2C (~200 GB/s) — the source of ~10 ms of hidden traffic in
    // every prior round, and of R13's wrong-memory corruption.
    void* p;
    cudaGetSymbolAddress(&p, g_h);
    float* gh = (float*)p;
    cudaGetSymbolAddress(&p, g_z);
    float* gz = (float*)p;

    const int NB = (NN + 255) / 256;
    const int PG128 = 148 * 16;
    const int PG256 = 148 * 8;

    k_initdeg<<<INITB + NB, 256>>>(out);       // 0
    k_scanall<<<1, 1024>>>(ei);                // 1
    k_fill<<<EB, 256>>>(ei);                   // 2
    k_aggs<128><<<PG128, 128>>>(x, gz, 0);     // 3  [sentinel]
    {
        dim3 g(HH / 128, (NN + 127) / 128);
        k_tcgemm<<<g, 256>>>(gz, W1, b1, gh, NN, FF, HH);
    }
    // layer 2 agg: two half passes
    k_aggs<256><<<PG128, 128>>>(gh, gz, 0);
    k_aggs<256><<<PG128, 128>>>(gh, gz, 128);
    {
        dim3 g(HH / 128, (NN + 127) / 128);
        k_tcgemm<<<g, 256>>>(gz, W2, b2, gh, NN, HH, HH);
    }
    // layer 3 agg
    k_aggs<256><<<PG128, 128>>>(gh, gz, 0);
    k_aggs<256><<<PG128, 128>>>(gh, gz, 128);
    {
        dim3 g(CC / 128, (NN + 127) / 128);
        k_tcgemm<<<g, 256>>>(gz, W3, b3, gh, NN, HH, CC);
    }

    k_softmax<<<PG256, 256>>>(gh, out + OFF_S);

    k_hsintra<<<HSB + EB, 256>>>(x, Ws, ei);
    k_invs<<<NB, 256>>>();
    k_sagg<<<EB, 256>>>(ei);
    k_score<<<NB, 256>>>(bs);
    k_segidx<<<NB, 256>>>();
    k_pooladj<<<CC + EB, 256>>>(x, ei, out);

    (void)in_sizes; (void)n_in; (void)out_size;
}

// round 15
// speedup vs baseline: 8.6244x; 1.2496x over previous
#include <cuda_runtime.h>
#include <math.h>
#include <stdint.h>

#define NN 50000
#define FF 128
#define CC 512
#define EE 800000
#define HH 256

// Output layout: new_x [C,F], new_adj [C,C], new_batch [C], S [N,C]
#define OFF_ADJ   (CC*FF)
#define OFF_BATCH (OFF_ADJ + CC*CC)
#define OFF_S     (OFF_BATCH + CC)

#define EB ((EE + 255) / 256)
#define HSB ((NN * 32 + 255) / 256)
#define INITB 512

// ---------------- scratch ----------------------------------------------------
__device__ __align__(16) float g_h[(size_t)NN * CC];
__device__ __align__(16) float g_z[(size_t)NN * HH];
__device__ float g_inv[NN];
__device__ int   g_deg[NN];
__device__ int   g_off[NN + 1];
__device__ int   g_cur[NN];
__device__ int   g_csr_src[EE];
__device__ float g_csr_cf[EE];
__device__ int   g_cluster[NN];
__device__ float g_hs[NN];
__device__ int   g_sdeg[NN];
__device__ float g_invs[NN];
__device__ float g_sagg[NN];
__device__ float g_score[NN];
__device__ int   g_icnt[CC];
__device__ int   g_segkey[CC];
__device__ int   g_segidx[CC];

__device__ __forceinline__ int fkey(float f) {
    int b = __float_as_int(f);
    return b < 0 ? (b ^ 0x7FFFFFFF) : b;
}
__device__ __forceinline__ float fdec(int k) {
    return __int_as_float(k < 0 ? (k ^ 0x7FFFFFFF) : k);
}

// ---------------- fused init + g_deg zero ------------------------------------
__global__ void k_initdeg(float* out) {
    int bid = blockIdx.x;
    int t = threadIdx.x;
    if (bid < INITB) {
        int i = bid * 256 + t;
        int stride = INITB * 256;
        for (int j = i; j < NN; j += stride) { g_sdeg[j] = 0; g_sagg[j] = 0.f; }
        for (int j = i; j < CC; j += stride) {
            g_icnt[j] = 0; g_segkey[j] = (int)0x80000000; g_segidx[j] = NN;
            out[OFF_BATCH + j] = 0.f;
        }
        for (int j = i; j < CC * CC; j += stride) out[OFF_ADJ + j] = 0.f;
    } else {
        int zi = (bid - INITB) * 256 + t;
        if (zi < NN) g_deg[zi] = 0;
    }
}

// multi-block degree histogram (measured ~20us vs ~200us single-block)
__global__ void k_deg(const int* __restrict__ ei) {
    int e = blockIdx.x * blockDim.x + threadIdx.x;
    if (e < EE) atomicAdd(&g_deg[ei[EE + e]], 1);
}

// single block: exclusive scan + inv + cur only
__global__ void __launch_bounds__(1024) k_scan() {
    __shared__ int ssum[1024];
    int t = threadIdx.x;
    const int chunk = (NN + 1023) / 1024;
    int b = t * chunk, e = min(b + chunk, NN);
    int s = 0;
    for (int i = b; i < e; i++) s += g_deg[i];
    ssum[t] = s;
    __syncthreads();
    for (int off = 1; off < 1024; off <<= 1) {
        int v = (t >= off) ? ssum[t - off] : 0;
        __syncthreads();
        ssum[t] += v;
        __syncthreads();
    }
    int run = (t > 0) ? ssum[t - 1] : 0;
    for (int i = b; i < e; i++) {
        int d = g_deg[i];
        g_off[i] = run;
        g_cur[i] = run;
        g_inv[i] = rsqrtf((float)d + 1.0f);
        run += d;
    }
    if (t == 1023) g_off[NN] = ssum[1023];
}

__global__ void k_fill(const int* __restrict__ ei) {
    int e = blockIdx.x * blockDim.x + threadIdx.x;
    if (e >= EE) return;
    int s = ei[e], d = ei[EE + e];
    int p = atomicAdd(&g_cur[d], 1);
    g_csr_src[p] = s;
    g_csr_cf[p] = g_inv[s] * g_inv[d];
}

// ---------------- aggregation: 128-wide slice pass, persistent ---------------
template <int STRIDE>
__global__ void __launch_bounds__(128) k_aggs(const float* __restrict__ h,
                                              float* __restrict__ z,
                                              int foff) {
    int t = threadIdx.x;
    const float* hf = h + foff + t;
    for (int i = blockIdx.x; i < NN; i += gridDim.x) {
        int beg = g_off[i], end = g_off[i + 1];
        float inv = g_inv[i];
        float acc0 = inv * inv * __ldg(hf + (size_t)i * STRIDE);
        float acc1 = 0.f;

        int j = beg;
        for (; j + 8 <= end; j += 8) {
            int s0 = __ldg(g_csr_src + j + 0);
            int s1 = __ldg(g_csr_src + j + 1);
            int s2 = __ldg(g_csr_src + j + 2);
            int s3 = __ldg(g_csr_src + j + 3);
            int s4 = __ldg(g_csr_src + j + 4);
            int s5 = __ldg(g_csr_src + j + 5);
            int s6 = __ldg(g_csr_src + j + 6);
            int s7 = __ldg(g_csr_src + j + 7);
            float c0 = __ldg(g_csr_cf + j + 0);
            float c1 = __ldg(g_csr_cf + j + 1);
            float c2 = __ldg(g_csr_cf + j + 2);
            float c3 = __ldg(g_csr_cf + j + 3);
            float c4 = __ldg(g_csr_cf + j + 4);
            float c5 = __ldg(g_csr_cf + j + 5);
            float c6 = __ldg(g_csr_cf + j + 6);
            float c7 = __ldg(g_csr_cf + j + 7);
            float v0 = __ldg(hf + (size_t)s0 * STRIDE);
            float v1 = __ldg(hf + (size_t)s1 * STRIDE);
            float v2 = __ldg(hf + (size_t)s2 * STRIDE);
            float v3 = __ldg(hf + (size_t)s3 * STRIDE);
            float v4 = __ldg(hf + (size_t)s4 * STRIDE);
            float v5 = __ldg(hf + (size_t)s5 * STRIDE);
            float v6 = __ldg(hf + (size_t)s6 * STRIDE);
            float v7 = __ldg(hf + (size_t)s7 * STRIDE);
            acc0 = fmaf(c0, v0, acc0); acc1 = fmaf(c1, v1, acc1);
            acc0 = fmaf(c2, v2, acc0); acc1 = fmaf(c3, v3, acc1);
            acc0 = fmaf(c4, v4, acc0); acc1 = fmaf(c5, v5, acc1);
            acc0 = fmaf(c6, v6, acc0); acc1 = fmaf(c7, v7, acc1);
        }
        for (; j < end; j++) {
            int s0 = __ldg(g_csr_src + j);
            float c0 = __ldg(g_csr_cf + j);
            acc0 = fmaf(c0, __ldg(hf + (size_t)s0 * STRIDE), acc0);
        }
        z[(size_t)i * STRIDE + foff + t] = acc0 + acc1;
    }
}

// ---------------- split-tf32 TC GEMM, software-pipelined ---------------------
__device__ __forceinline__ uint32_t f2tf(float f) {
    uint32_t r;
    asm("cvt.rna.tf32.f32 %0, %1;" : "=r"(r) : "f"(f));
    return r;
}
__device__ __forceinline__ void mma_tf32(float4& d,
                                         uint32_t a0, uint32_t a1, uint32_t a2, uint32_t a3,
                                         uint32_t b0, uint32_t b1) {
    asm volatile("mma.sync.aligned.m16n8k8.row.col.f32.tf32.tf32.f32 "
                 "{%0,%1,%2,%3}, {%4,%5,%6,%7}, {%8,%9}, {%0,%1,%2,%3};"
                 : "+f"(d.x), "+f"(d.y), "+f"(d.z), "+f"(d.w)
                 : "r"(a0), "r"(a1), "r"(a2), "r"(a3), "r"(b0), "r"(b1));
}

#define TCSTRIDE 136

__global__ void __launch_bounds__(256) k_tcgemm(const float* __restrict__ A,
                                                const float* __restrict__ B,
                                                const float* __restrict__ bias,
                                                float* __restrict__ Cm,
                                                int M, int K, int Nc) {
    __shared__ uint32_t Ah[2][8][TCSTRIDE];
    __shared__ uint32_t Al[2][8][TCSTRIDE];
    __shared__ uint32_t Bh[2][8][TCSTRIDE];
    __shared__ uint32_t Bl[2][8][TCSTRIDE];

    const int tid = threadIdx.x;
    const int wid = tid >> 5;
    const int lane = tid & 31;
    const int q = lane >> 2;
    const int t4 = lane & 3;
    const int m0 = (wid & 3) * 32;
    const int n0 = (wid >> 2) * 64;

    const int rowBase = blockIdx.y * 128;
    const int colBase = blockIdx.x * 128;

    const int ar = tid >> 1;
    const int ac4 = (tid & 1) * 4;
    const int br = tid >> 5;
    const int bc4 = (tid & 31) * 4;
    const bool aok = (rowBase + ar) < M;
    const float* Aptr = A + (size_t)(rowBase + ar) * K + ac4;
    const float* Bptr = B + (size_t)br * Nc + colBase + bc4;

    float4 acc[2][8];
#pragma unroll
    for (int mi = 0; mi < 2; mi++)
#pragma unroll
        for (int ni = 0; ni < 8; ni++) acc[mi][ni] = make_float4(0.f, 0.f, 0.f, 0.f);

#define SPLIT_STORE(arrH, arrL, BUF, D0, D1, V)                      \
    {                                                                \
        uint32_t h_ = f2tf(V);                                       \
        float lo_ = (V) - __uint_as_float(h_);                       \
        arrH[BUF][D0][D1] = h_;                                      \
        arrL[BUF][D0][D1] = f2tf(lo_);                               \
    }
#define STORE_TILE(BUF, VA, VB)                                                   \
    {                                                                             \
        SPLIT_STORE(Ah, Al, BUF, ac4 + 0, ar, (VA).x)                             \
        SPLIT_STORE(Ah, Al, BUF, ac4 + 1, ar, (VA).y)                             \
        SPLIT_STORE(Ah, Al, BUF, ac4 + 2, ar, (VA).z)                             \
        SPLIT_STORE(Ah, Al, BUF, ac4 + 3, ar, (VA).w)                             \
        SPLIT_STORE(Bh, Bl, BUF, br, bc4 + 0, (VB).x)                             \
        SPLIT_STORE(Bh, Bl, BUF, br, bc4 + 1, (VB).y)                             \
        SPLIT_STORE(Bh, Bl, BUF, br, bc4 + 2, (VB).z)                             \
        SPLIT_STORE(Bh, Bl, BUF, br, bc4 + 3, (VB).w)                             \
    }

#define COMPUTE_TILE(BUF)                                                          \
    {                                                                              \
        uint32_t ah[2][4], al[2][4];                                               \
        _Pragma("unroll")                                                          \
        for (int mi = 0; mi < 2; mi++) {                                           \
            int mrow = m0 + mi * 16;                                               \
            ah[mi][0] = Ah[BUF][t4][mrow + q];                                     \
            ah[mi][1] = Ah[BUF][t4][mrow + q + 8];                                 \
            ah[mi][2] = Ah[BUF][t4 + 4][mrow + q];                                 \
            ah[mi][3] = Ah[BUF][t4 + 4][mrow + q + 8];                             \
            al[mi][0] = Al[BUF][t4][mrow + q];                                     \
            al[mi][1] = Al[BUF][t4][mrow + q + 8];                                 \
            al[mi][2] = Al[BUF][t4 + 4][mrow + q];                                 \
            al[mi][3] = Al[BUF][t4 + 4][mrow + q + 8];                             \
        }                                                                          \
        _Pragma("unroll")                                                          \
        for (int ni = 0; ni < 8; ni++) {                                           \
            int ncol = n0 + ni * 8 + q;                                            \
            uint32_t bh0 = Bh[BUF][t4][ncol];                                      \
            uint32_t bh1 = Bh[BUF][t4 + 4][ncol];                                  \
            uint32_t bl0 = Bl[BUF][t4][ncol];                                      \
            uint32_t bl1 = Bl[BUF][t4 + 4][ncol];                                  \
            _Pragma("unroll")                                                      \
            for (int mi = 0; mi < 2; mi++) {                                       \
                mma_tf32(acc[mi][ni], ah[mi][0], ah[mi][1], ah[mi][2], ah[mi][3],  \
                         bh0, bh1);                                                \
                mma_tf32(acc[mi][ni], ah[mi][0], ah[mi][1], ah[mi][2], ah[mi][3],  \
                         bl0, bl1);                                                \
                mma_tf32(acc[mi][ni], al[mi][0], al[mi][1], al[mi][2], al[mi][3],  \
                         bh0, bh1);                                                \
            }                                                                      \
        }                                                                          \
    }

    {
        float4 va = aok ? *(const float4*)Aptr : make_float4(0.f, 0.f, 0.f, 0.f);
        float4 vb = *(const float4*)Bptr;
        STORE_TILE(0, va, vb)
    }
    __syncthreads();

    int buf = 0;
    for (int k0 = 8; k0 < K; k0 += 8) {
        float4 va = aok ? *(const float4*)(Aptr + k0) : make_float4(0.f, 0.f, 0.f, 0.f);
        float4 vb = *(const float4*)(Bptr + (size_t)k0 * Nc);
        COMPUTE_TILE(buf)
        STORE_TILE(buf ^ 1, va, vb)
        __syncthreads();
        buf ^= 1;
    }
    COMPUTE_TILE(buf)

#pragma unroll
    for (int mi = 0; mi < 2; mi++) {
#pragma unroll
        for (int ni = 0; ni < 8; ni++) {
            int col = colBase + n0 + ni * 8 + 2 * t4;
            float bb0 = bias[col], bb1 = bias[col + 1];
            int r0 = rowBase + m0 + mi * 16 + q;
            int r1 = r0 + 8;
            float4 v = acc[mi][ni];
            float o0 = fmaxf(v.x + bb0, 0.f);
            float o1 = fmaxf(v.y + bb1, 0.f);
            float o2 = fmaxf(v.z + bb0, 0.f);
            float o3 = fmaxf(v.w + bb1, 0.f);
            if (r0 < M) *(float2*)(Cm + (size_t)r0 * Nc + col) = make_float2(o0, o1);
            if (r1 < M) *(float2*)(Cm + (size_t)r1 * Nc + col) = make_float2(o2, o3);
        }
    }
}

// ---------------- softmax + argmax: persistent grid-stride -------------------
__global__ void __launch_bounds__(256) k_softmax(const float* __restrict__ logits,
                                                 float* __restrict__ S) {
    int t = threadIdx.x;
    __shared__ float sv[256];
    __shared__ int   si[256];
    for (int i = blockIdx.x; i < NN; i += gridDim.x) {
        const float* row = logits + (size_t)i * CC;
        float v0 = row[t], v1 = row[t + 256];
        float bv = v0; int bi = t;
        if (v1 > bv) { bv = v1; bi = t + 256; }

        sv[t] = bv; si[t] = bi;
        __syncthreads();
        for (int s = 128; s > 0; s >>= 1) {
            if (t < s) {
                float ov = sv[t + s]; int oi = si[t + s];
                if (ov > sv[t] || (ov == sv[t] && oi < si[t])) { sv[t] = ov; si[t] = oi; }
            }
            __syncthreads();
        }
        float m = sv[0];
        if (t == 0) g_cluster[i] = si[0];
        __syncthreads();

        float e0 = expf(v0 - m), e1 = expf(v1 - m);
        sv[t] = e0 + e1;
        __syncthreads();
        for (int s = 128; s > 0; s >>= 1) {
            if (t < s) sv[t] += sv[t + s];
            __syncthreads();
        }
        float invsum = 1.0f / sv[0];
        S[(size_t)i * CC + t]       = e0 * invsum;
        S[(size_t)i * CC + t + 256] = e1 * invsum;
        __syncthreads();
    }
}

// ---------------- fused: hs (x@Ws) + intradeg --------------------------------
__global__ void k_hsintra(const float* __restrict__ x,
                          const float* __restrict__ Ws,
                          const int* __restrict__ ei) {
    int bid = blockIdx.x;
    int t = threadIdx.x;
    if (bid < HSB) {
        int g = bid * 256 + t;
        int w = g >> 5, lane = g & 31;
        if (w >= NN) return;
        float s = 0.f;
        for (int f = lane; f < FF; f += 32) s = fmaf(x[(size_t)w * FF + f], Ws[f], s);
#pragma unroll
        for (int off = 16; off > 0; off >>= 1) s += __shfl_down_sync(0xFFFFFFFF, s, off);
        if (lane == 0) g_hs[w] = s;
    } else {
        int e = (bid - HSB) * 256 + t;
        if (e >= EE) return;
        int s = ei[e], d = ei[EE + e];
        int cs = g_cluster[s], cd = g_cluster[d];
        if (cs == cd) {
            atomicAdd(&g_sdeg[d], 1);
            atomicAdd(&g_icnt[cs], 1);
        }
    }
}

__global__ void k_invs() {
    int i = blockIdx.x * blockDim.x + threadIdx.x;
    if (i < NN) g_invs[i] = rsqrtf((float)g_sdeg[i] + 1.0f);
}

__global__ void k_sagg(const int* __restrict__ ei) {
    int e = blockIdx.x * blockDim.x + threadIdx.x;
    if (e >= EE) return;
    int s = ei[e], d = ei[EE + e];
    if (g_cluster[s] == g_cluster[d])
        atomicAdd(&g_sagg[d], g_invs[s] * g_invs[d] * g_hs[s]);
}

__global__ void k_score(const float* __restrict__ bs) {
    int i = blockIdx.x * blockDim.x + threadIdx.x;
    if (i >= NN) return;
    float inv = g_invs[i];
    float v = g_sagg[i] + inv * inv * g_hs[i] + bs[0];
    float sc = tanhf(v);
    g_score[i] = sc;
    atomicMax(&g_segkey[g_cluster[i]], fkey(sc));
}

__global__ void k_segidx() {
    int i = blockIdx.x * blockDim.x + threadIdx.x;
    if (i >= NN) return;
    int c = g_cluster[i];
    float mx = fdec(g_segkey[c]);
    if (g_score[i] >= mx) atomicMin(&g_segidx[c], i);
}

// ---------------- fused: pool + adjacency ------------------------------------
__global__ void k_pooladj(const float* __restrict__ x,
                          const int* __restrict__ ei,
                          float* __restrict__ out) {
    int bid = blockIdx.x;
    int t = threadIdx.x;
    if (bid < CC) {
        if (t < 128) {
            int c = bid;
            bool ne = g_icnt[c] > 0;
            float alpha = ne ? fdec(g_segkey[c]) : 0.f;
            int idx = min(g_segidx[c], NN - 1);
            out[(size_t)c * FF + t] = x[(size_t)idx * FF + t] * alpha;
        }
    } else {
        int e = (bid - CC) * 256 + t;
        if (e >= EE) return;
        int cs = g_cluster[ei[e]], cd = g_cluster[ei[EE + e]];
        if (cs != cd && g_icnt[cs] > 0 && g_icnt[cd] > 0)
            out[OFF_ADJ + (size_t)cs * CC + cd] = 1.0f;
    }
}

// ---------------- launch ------------------------------------------------------
extern "C" void kernel_launch(void* const* d_in, const int* in_sizes, int n_in,
                              void* d_out, int out_size) {
    const float* x   = (const float*)d_in[0];
    const int*   ei  = (const int*)d_in[1];
    const float* W1  = (const float*)d_in[3];
    const float* b1  = (const float*)d_in[4];
    const float* W2  = (const float*)d_in[5];
    const float* b2  = (const float*)d_in[6];
    const float* W3  = (const float*)d_in[7];
    const float* b3  = (const float*)d_in[8];
    const float* Ws  = (const float*)d_in[9];
    const float* bs  = (const float*)d_in[10];
    float* out = (float*)d_out;

    // TRUE device addresses of scratch symbols (host array names decay to the
    // host shadow, which ATS serves from HOST memory over C2C at ~200 GB/s).
    void* p;
    cudaGetSymbolAddress(&p, g_h);
    float* gh = (float*)p;
    cudaGetSymbolAddress(&p, g_z);
    float* gz = (float*)p;

    const int NB = (NN + 255) / 256;
    const int PG128 = 148 * 16;
    const int PG256 = 148 * 8;

    k_initdeg<<<INITB + NB, 256>>>(out);       // 0
    k_deg<<<EB, 256>>>(ei);                    // 1 (multi-block histogram)
    k_scan<<<1, 1024>>>();                     // 2 (scan + inv + cur)
    k_fill<<<EB, 256>>>(ei);                   // 3
    k_aggs<128><<<PG128, 128>>>(x, gz, 0);
    {
        dim3 g(HH / 128, (NN + 127) / 128);
        k_tcgemm<<<g, 256>>>(gz, W1, b1, gh, NN, FF, HH);
    }
    k_aggs<256><<<PG128, 128>>>(gh, gz, 0);
    k_aggs<256><<<PG128, 128>>>(gh, gz, 128);
    {
        dim3 g(HH / 128, (NN + 127) / 128);
        k_tcgemm<<<g, 256>>>(gz, W2, b2, gh, NN, HH, HH);
    }
    k_aggs<256><<<PG128, 128>>>(gh, gz, 0);
    k_aggs<256><<<PG128, 128>>>(gh, gz, 128);
    {
        dim3 g(CC / 128, (NN + 127) / 128);
        k_tcgemm<<<g, 256>>>(gz, W3, b3, gh, NN, HH, CC);
    }

    k_softmax<<<PG256, 256>>>(gh, out + OFF_S);

    k_hsintra<<<HSB + EB, 256>>>(x, Ws, ei);
    k_invs<<<NB, 256>>>();
    k_sagg<<<EB, 256>>>(ei);
    k_score<<<NB, 256>>>(bs);
    k_segidx<<<NB, 256>>>();
    k_pooladj<<<CC + EB, 256>>>(x, ei, out);

    (void)in_sizes; (void)n_in; (void)out_size;
}